// round 12
// baseline (speedup 1.0000x reference)
#include <cuda_runtime.h>
#include <math.h>
#include <stdint.h>

#define BB    1024     // batch rows
#define NN    8192     // samples per row
#define MM2   900      // half fold period (parity decimation)
#define NB    140      // bpm bins
#define NBP   144      // padded bins
#define NCH   9        // m-chunks
#define CHM   100      // m per chunk (9*100 = 900)
#define SLAB  10       // m per smem slab

// ---------------- device scratch ----------------
__device__ float2 d_fold[(size_t)BB * MM2];             // (ge, go)
__device__ float2 d_part[(size_t)BB * NCH * NBP];       // [row][chunk][bin] (s,c)
__device__ float  d_tl[BB];
__device__ float  d_fl[BB];

typedef unsigned long long ull;

// ---------------- f32x2 helpers ----------------
__device__ __forceinline__ ull pk2(float lo, float hi) {
    ull r;
    asm("mov.b64 %0, {%1, %2};" : "=l"(r) : "f"(lo), "f"(hi));
    return r;
}
__device__ __forceinline__ void fma2(ull& d, ull a, ull b) {
    asm("fma.rn.f32x2 %0, %1, %2, %0;" : "+l"(d) : "l"(a), "l"(b));
}

// ---------------- warp helpers ----------------
__device__ __forceinline__ float wsum(float v) {
    #pragma unroll
    for (int o = 16; o; o >>= 1) v += __shfl_down_sync(0xffffffffu, v, o);
    return v;
}
__device__ __forceinline__ float wallsum(float v) {
    #pragma unroll
    for (int o = 16; o; o >>= 1) v += __shfl_xor_sync(0xffffffffu, v, o);
    return v;
}
__device__ __forceinline__ float wallmax(float v) {
    #pragma unroll
    for (int o = 16; o; o >>= 1) v = fmaxf(v, __shfl_xor_sync(0xffffffffu, v, o));
    return v;
}

// ---------------- K1: pearson + parity fold, float4 (unchanged from R11) -----
__global__ void __launch_bounds__(256) k_fold(const float* __restrict__ x,
                                              const float* __restrict__ y) {
    __shared__ float red[8][5];
    int b = blockIdx.x;
    int tid = threadIdx.x;
    int lane = tid & 31, warp = tid >> 5;

    const float4* xr = (const float4*)(x + (size_t)b * NN);
    const float4* yr = (const float4*)(y + (size_t)b * NN);
    const float W = 3.8349520e-4f;          // pi/8191

    float sx = 0.f, sy = 0.f, sxy = 0.f, sxx = 0.f, syy = 0.f;
    float ge[4] = {}, go[4] = {};

    if (tid < 225) {
        #pragma unroll
        for (int j = 0; j < 10; j++) {
            int q = tid + 225 * j;
            if (j < 9 || q < 2048) {
                float4 xv = xr[q];
                float4 yv = yr[q];
                sx += xv.x + xv.y + xv.z + xv.w;
                sy += yv.x + yv.y + yv.z + yv.w;
                sxy += xv.x*yv.x + xv.y*yv.y + xv.z*yv.z + xv.w*yv.w;
                sxx += xv.x*xv.x + xv.y*xv.y + xv.z*xv.z + xv.w*xv.w;
                syy += yv.x*yv.x + yv.y*yv.y + yv.z*yv.z + yv.w*yv.w;
                int n = 4 * q;
                float s0 = __sinf((float)(n)     * W);
                float s1 = __sinf((float)(n + 1) * W);
                float s2 = __sinf((float)(n + 2) * W);
                float s3 = __sinf((float)(n + 3) * W);
                float h0 = xv.x * s0 * s0, h1 = xv.y * s1 * s1;
                float h2 = xv.z * s2 * s2, h3 = xv.w * s3 * s3;
                ge[0] += h0; ge[1] += h1; ge[2] += h2; ge[3] += h3;
                if (j & 1) { go[0] -= h0; go[1] -= h1; go[2] -= h2; go[3] -= h3; }
                else       { go[0] += h0; go[1] += h1; go[2] += h2; go[3] += h3; }
            }
        }
        float4* dst = (float4*)(d_fold + (size_t)b * MM2 + 4 * tid);
        dst[0] = make_float4(ge[0], go[0], ge[1], go[1]);
        dst[1] = make_float4(ge[2], go[2], ge[3], go[3]);
    }

    sx = wsum(sx); sy = wsum(sy); sxy = wsum(sxy); sxx = wsum(sxx); syy = wsum(syy);
    if (lane == 0) { red[warp][0]=sx; red[warp][1]=sy; red[warp][2]=sxy; red[warp][3]=sxx; red[warp][4]=syy; }
    __syncthreads();
    if (tid == 0) {
        double SX=0, SY=0, SXY=0, SXX=0, SYY=0;
        #pragma unroll
        for (int w = 0; w < 8; w++) {
            SX += red[w][0]; SY += red[w][1]; SXY += red[w][2];
            SXX += red[w][3]; SYY += red[w][4];
        }
        double num = (double)NN * SXY - SX * SY;
        double den = sqrt(((double)NN * SXX - SX * SX) * ((double)NN * SYY - SY * SY));
        d_tl[b] = (float)(1.0 - num / den);
    }
}

// ---------------- K2: parity NUDFT; split sin/cos planes (conflict-free) -----
// grid (32 tiles, 9 chunks), block 288 = 36 tx * 8 ty; tile 4 rows x 4 bins
__global__ void __launch_bounds__(288, 2) k_dft() {
    __shared__ float sSin[SLAB][NBP];     // 10 m x 144 bins, 4B stride (LDS.32)
    __shared__ float sCos[SLAB][NBP];
    __shared__ float sGe[SLAB][32];
    __shared__ float sGo[SLAB][32];

    int tile  = blockIdx.x;
    int chunk = blockIdx.y;
    int tid = threadIdx.x;
    int tx = tid % 36;
    int ty = tid / 36;

    int rowBase = tile * 32;
    int mBase = chunk * CHM;

    int bk  = tid % NBP;
    int grp = tid / NBP;
    int freq = 40 + bk;

    ull acc[4][4] = {};
    const float* gp = (tx & 1) ? &sGo[0][0] : &sGe[0][0];
    const float ASCALE = 3.4906585e-3f;   // 2*pi/1800

    for (int step = 0; step < CHM / SLAB; step++) {
        int m0 = mBase + step * SLAB;
        __syncthreads();
        #pragma unroll
        for (int i = 0; i < 5; i++) {
            int mi = grp * 5 + i;
            float s = 0.f, c = 0.f;
            if (bk < NB) {
                int r = (freq * (m0 + mi)) % 1800;
                if (r >= 900) r -= 1800;
                __sincosf((float)r * ASCALE, &s, &c);
            }
            sSin[mi][bk] = s;
            sCos[mi][bk] = c;
        }
        if (tid < 160) {
            int r = tid & 31, q = tid >> 5;
            float4 v = *(const float4*)(d_fold + (size_t)(rowBase + r) * MM2 + m0 + 2 * q);
            sGe[2 * q][r]     = v.x;  sGo[2 * q][r]     = v.y;
            sGe[2 * q + 1][r] = v.z;  sGo[2 * q + 1][r] = v.w;
        }
        __syncthreads();

        #pragma unroll
        for (int mi = 0; mi < SLAB; mi++) {
            float4 g = *(const float4*)&gp[mi * 32 + 4 * ty];
            // dense LDS.32 (conflict-free) + register pack for fma2
            float s0 = sSin[mi][tx],       c0 = sCos[mi][tx];
            float s1 = sSin[mi][tx + 36],  c1 = sCos[mi][tx + 36];
            float s2 = sSin[mi][tx + 72],  c2 = sCos[mi][tx + 72];
            float s3 = sSin[mi][tx + 108], c3 = sCos[mi][tx + 108];
            ull p0 = pk2(s0, c0);
            ull p1 = pk2(s1, c1);
            ull p2 = pk2(s2, c2);
            ull p3 = pk2(s3, c3);
            float gr[4] = {g.x, g.y, g.z, g.w};
            #pragma unroll
            for (int r = 0; r < 4; r++) {
                ull g2 = pk2(gr[r], gr[r]);
                fma2(acc[r][0], g2, p0);
                fma2(acc[r][1], g2, p1);
                fma2(acc[r][2], g2, p2);
                fma2(acc[r][3], g2, p3);
            }
        }
    }

    #pragma unroll
    for (int r = 0; r < 4; r++) {
        int row = rowBase + 4 * ty + r;
        ull* dst = (ull*)(d_part + ((size_t)row * NCH + chunk) * NBP);
        dst[tx]       = acc[r][0];
        dst[tx + 36]  = acc[r][1];
        dst[tx + 72]  = acc[r][2];
        dst[tx + 108] = acc[r][3];
    }
}

// ---------------- K3: one block per row; thread = bin (unchanged) ------------
#define LT 160   // threads (5 warps); bins 0..143 active
__global__ void __launch_bounds__(LT) k_loss(const int* __restrict__ hr) {
    __shared__ float sh[8];
    __shared__ float shH;
    int tid = threadIdx.x;
    int lane = tid & 31, warp = tid >> 5;
    int row = blockIdx.x;
    bool valid = tid < NB;

    float s = 0.f, c = 0.f;
    if (valid) {
        const float2* pr = d_part + (size_t)row * NCH * NBP + tid;
        #pragma unroll
        for (int ch = 0; ch < NCH; ch++) {
            float2 v = pr[ch * NBP];
            s += v.x; c += v.y;
        }
    }
    float ca = valid ? (s * s + c * c) : 0.f;

    float v = wallsum(ca);
    if (lane == 0) sh[warp] = v;
    __syncthreads();
    float tot = sh[0] + sh[1] + sh[2] + sh[3] + sh[4];
    __syncthreads();

    float logit = ca / tot;

    v = wallmax(valid ? logit : -1e30f);
    if (lane == 0) sh[warp] = v;
    __syncthreads();
    float mx = fmaxf(fmaxf(fmaxf(sh[0], sh[1]), fmaxf(sh[2], sh[3])), sh[4]);
    __syncthreads();

    v = wallsum(valid ? expf(logit - mx) : 0.f);
    if (lane == 0) sh[warp] = v;
    __syncthreads();
    float lse = mx + logf(sh[0] + sh[1] + sh[2] + sh[3] + sh[4]);

    int h = hr[row];
    if (tid == h) shH = logit;
    __syncthreads();
    float ce = lse - shH;
    __syncthreads();

    float klc = 0.f;
    if (valid) {
        float dd = (float)tid - (float)h;
        float t = expf(-0.5f * dd * dd) * 0.3989422804014327f;
        t = fmaxf(t, 1e-15f);
        klc = expf(t) * (t - (logit - lse));
    }
    v = wallsum(klc);
    if (lane == 0) sh[warp] = v;
    __syncthreads();
    if (tid == 0) d_fl[row] = ce + (sh[0] + sh[1] + sh[2] + sh[3] + sh[4]) / (float)NB;
}

// ---------------- K4: final scalar (unchanged) ----------------
__global__ void __launch_bounds__(1024) k_final(const int* __restrict__ epoch_p,
                                                float* __restrict__ out) {
    __shared__ float r1[32], r2[32];
    int tid = threadIdx.x, lane = tid & 31, warp = tid >> 5;
    float a = d_tl[tid], c = d_fl[tid];
    a = wsum(a); c = wsum(c);
    if (lane == 0) { r1[warp] = a; r2[warp] = c; }
    __syncthreads();
    if (warp == 0) {
        a = wsum(r1[lane]);
        c = wsum(r2[lane]);
        if (lane == 0) {
            float tl = a / (float)BB;
            float fl = c / (float)BB;
            int epoch = epoch_p[0];
            float alpha, beta;
            if (epoch > 25) { alpha = 0.05f; beta = 2.0f; }
            else {
                float e = (float)epoch * 0.04f;       // epoch/25
                alpha = 0.1f * exp2f(-e);
                beta  = exp2f(e);
            }
            out[0] = alpha * tl + beta * fl;
        }
    }
}

// ---------------- launch ----------------
extern "C" void kernel_launch(void* const* d_in, const int* in_sizes, int n_in,
                              void* d_out, int out_size) {
    const int*   epoch_p = nullptr;
    const float* xp = nullptr;
    const float* yp = nullptr;
    const int*   hrp = nullptr;
    for (int i = 0; i < n_in; i++) {
        if (in_sizes[i] == 1 && !epoch_p) epoch_p = (const int*)d_in[i];
        else if (in_sizes[i] == BB * NN) { if (!xp) xp = (const float*)d_in[i]; else yp = (const float*)d_in[i]; }
        else if (in_sizes[i] == BB) hrp = (const int*)d_in[i];
    }
    float* out = (float*)d_out;

    k_fold<<<BB, 256>>>(xp, yp);
    k_dft<<<dim3(32, NCH), 288>>>();
    k_loss<<<BB, LT>>>(hrp);
    k_final<<<1, 1024>>>(epoch_p, out);
    (void)out_size;
}

// round 13
// speedup vs baseline: 1.1965x; 1.1965x over previous
#include <cuda_runtime.h>
#include <math.h>
#include <stdint.h>

#define BB    1024     // batch rows
#define NN    8192     // samples per row
#define MM2   900      // parity-fold period
#define MM3   486      // reflection-folded m range (451 used, padded to 9*54)
#define NB    140      // bpm bins
#define NBP   144      // padded bins
#define NCH   9        // m-chunks
#define CHM   54       // m per chunk (9*54 = 486)
#define SLAB  9        // m per smem slab (6 steps)

// ---------------- device scratch ----------------
__device__ float4 d_fold[(size_t)BB * MM3];             // (ve,ue,vo,uo) per (row,m)
__device__ float2 d_part[(size_t)BB * NCH * NBP];       // [row][chunk][bin] (S,C)
__device__ float  d_tl[BB];
__device__ float  d_fl[BB];

typedef unsigned long long ull;

// ---------------- f32x2 helpers ----------------
__device__ __forceinline__ ull pk2(float lo, float hi) {
    ull r;
    asm("mov.b64 %0, {%1, %2};" : "=l"(r) : "f"(lo), "f"(hi));
    return r;
}
__device__ __forceinline__ void fma2(ull& d, ull a, ull b) {
    asm("fma.rn.f32x2 %0, %1, %2, %0;" : "+l"(d) : "l"(a), "l"(b));
}

// ---------------- warp helpers ----------------
__device__ __forceinline__ float wsum(float v) {
    #pragma unroll
    for (int o = 16; o; o >>= 1) v += __shfl_down_sync(0xffffffffu, v, o);
    return v;
}
__device__ __forceinline__ float wallsum(float v) {
    #pragma unroll
    for (int o = 16; o; o >>= 1) v += __shfl_xor_sync(0xffffffffu, v, o);
    return v;
}
__device__ __forceinline__ float wallmax(float v) {
    #pragma unroll
    for (int o = 16; o; o >>= 1) v = fmaxf(v, __shfl_xor_sync(0xffffffffu, v, o));
    return v;
}

// ---------------- K1: pearson + parity fold + reflection combos --------------
// thread t<225 computes ge/go for m in {4t..4t+3}; stage in smem; emit combos
__global__ void __launch_bounds__(256) k_fold(const float* __restrict__ x,
                                              const float* __restrict__ y) {
    __shared__ float sge[MM2];
    __shared__ float sgo[MM2];
    __shared__ float red[8][5];
    int b = blockIdx.x;
    int tid = threadIdx.x;
    int lane = tid & 31, warp = tid >> 5;

    const float4* xr = (const float4*)(x + (size_t)b * NN);
    const float4* yr = (const float4*)(y + (size_t)b * NN);
    const float W = 3.8349520e-4f;          // pi/8191

    float sx = 0.f, sy = 0.f, sxy = 0.f, sxx = 0.f, syy = 0.f;
    float ge[4] = {}, go[4] = {};

    if (tid < 225) {
        #pragma unroll
        for (int j = 0; j < 10; j++) {
            int q = tid + 225 * j;
            if (j < 9 || q < 2048) {
                float4 xv = xr[q];
                float4 yv = yr[q];
                sx += xv.x + xv.y + xv.z + xv.w;
                sy += yv.x + yv.y + yv.z + yv.w;
                sxy += xv.x*yv.x + xv.y*yv.y + xv.z*yv.z + xv.w*yv.w;
                sxx += xv.x*xv.x + xv.y*xv.y + xv.z*xv.z + xv.w*xv.w;
                syy += yv.x*yv.x + yv.y*yv.y + yv.z*yv.z + yv.w*yv.w;
                int n = 4 * q;
                float s0 = __sinf((float)(n)     * W);
                float s1 = __sinf((float)(n + 1) * W);
                float s2 = __sinf((float)(n + 2) * W);
                float s3 = __sinf((float)(n + 3) * W);
                float h0 = xv.x * s0 * s0, h1 = xv.y * s1 * s1;
                float h2 = xv.z * s2 * s2, h3 = xv.w * s3 * s3;
                ge[0] += h0; ge[1] += h1; ge[2] += h2; ge[3] += h3;
                if (j & 1) { go[0] -= h0; go[1] -= h1; go[2] -= h2; go[3] -= h3; }
                else       { go[0] += h0; go[1] += h1; go[2] += h2; go[3] += h3; }
            }
        }
        #pragma unroll
        for (int k = 0; k < 4; k++) {
            sge[4 * tid + k] = ge[k];
            sgo[4 * tid + k] = go[k];
        }
    }
    __syncthreads();

    // reflection combos: even f: (v,u)=(g[m]-g[900-m], g[m]+g[900-m])
    //                    odd  f: (v,u)=(g[m]+g[900-m], g[m]-g[900-m])
    for (int m = tid; m < MM3; m += 256) {
        float4 o;
        if (m == 0) {
            o = make_float4(sge[0], sge[0], sgo[0], sgo[0]);   // sin(0)=0: v unused
        } else if (m < 450) {
            float a = sge[m], bb2 = sge[900 - m];
            float c = sgo[m], d  = sgo[900 - m];
            o = make_float4(a - bb2, a + bb2, c + d, c - d);
        } else if (m == 450) {
            o = make_float4(sge[450], sge[450], sgo[450], sgo[450]);
        } else {
            o = make_float4(0.f, 0.f, 0.f, 0.f);
        }
        d_fold[(size_t)b * MM3 + m] = o;
    }

    sx = wsum(sx); sy = wsum(sy); sxy = wsum(sxy); sxx = wsum(sxx); syy = wsum(syy);
    if (lane == 0) { red[warp][0]=sx; red[warp][1]=sy; red[warp][2]=sxy; red[warp][3]=sxx; red[warp][4]=syy; }
    __syncthreads();
    if (tid == 0) {
        double SX=0, SY=0, SXY=0, SXX=0, SYY=0;
        #pragma unroll
        for (int w = 0; w < 8; w++) {
            SX += red[w][0]; SY += red[w][1]; SXY += red[w][2];
            SXX += red[w][3]; SYY += red[w][4];
        }
        double num = (double)NN * SXY - SX * SY;
        double den = sqrt(((double)NN * SXX - SX * SX) * ((double)NN * SYY - SY * SY));
        d_tl[b] = (float)(1.0 - num / den);
    }
}

// ---------------- K2: reflected parity NUDFT (half FLOPs of R4) --------------
// grid (32 tiles, 9 chunks), block 288 = 36 tx * 8 ty; tile 4 rows x 4 bins
__global__ void __launch_bounds__(288, 2) k_dft() {
    __shared__ float sTab[SLAB * 2 * NBP];    // 9 m x 144 bins x (s,c) interleaved
    __shared__ ull   sGE[SLAB][32];           // (ve,ue) packed
    __shared__ ull   sGO[SLAB][32];           // (vo,uo) packed

    int tile  = blockIdx.x;
    int chunk = blockIdx.y;
    int tid = threadIdx.x;
    int tx = tid % 36;
    int ty = tid / 36;

    int rowBase = tile * 32;
    int mBase = chunk * CHM;

    int bk  = tid % NBP;
    int grp = tid / NBP;
    int freq = 40 + bk;

    ull acc[4][4] = {};
    const ull* gbase = (tx & 1) ? &sGO[0][0] : &sGE[0][0];
    const float ASCALE = 3.4906585e-3f;   // 2*pi/1800

    for (int step = 0; step < CHM / SLAB; step++) {
        int m0 = mBase + step * SLAB;
        __syncthreads();
        // table: 9 m x 144 bins; grp0 -> mi 0..4, grp1 -> mi 5..8
        #pragma unroll
        for (int i = 0; i < 5; i++) {
            int mi = grp * 5 + i;
            if (mi < SLAB) {
                float s = 0.f, c = 0.f;
                if (bk < NB) {
                    int r = (freq * (m0 + mi)) % 1800;
                    if (r >= 900) r -= 1800;
                    __sincosf((float)r * ASCALE, &s, &c);
                }
                sTab[mi * (2 * NBP) + 2 * bk]     = s;
                sTab[mi * (2 * NBP) + 2 * bk + 1] = c;
            }
        }
        // staging: exactly one float4 per thread (9 m x 32 rows = 288)
        {
            int r = tid & 31, mi = tid >> 5;
            float4 v = d_fold[(size_t)(rowBase + r) * MM3 + m0 + mi];
            sGE[mi][r] = pk2(v.x, v.y);
            sGO[mi][r] = pk2(v.z, v.w);
        }
        __syncthreads();

        #pragma unroll
        for (int mi = 0; mi < SLAB; mi++) {
            const ull* gq = gbase + mi * 32 + 4 * ty;
            ull g0 = gq[0], g1 = gq[1], g2 = gq[2], g3 = gq[3];
            const ull* trow = (const ull*)&sTab[mi * (2 * NBP)];
            ull p0 = trow[tx];
            ull p1 = trow[tx + 36];
            ull p2 = trow[tx + 72];
            ull p3 = trow[tx + 108];
            fma2(acc[0][0], g0, p0); fma2(acc[0][1], g0, p1);
            fma2(acc[0][2], g0, p2); fma2(acc[0][3], g0, p3);
            fma2(acc[1][0], g1, p0); fma2(acc[1][1], g1, p1);
            fma2(acc[1][2], g1, p2); fma2(acc[1][3], g1, p3);
            fma2(acc[2][0], g2, p0); fma2(acc[2][1], g2, p1);
            fma2(acc[2][2], g2, p2); fma2(acc[2][3], g2, p3);
            fma2(acc[3][0], g3, p0); fma2(acc[3][1], g3, p1);
            fma2(acc[3][2], g3, p2); fma2(acc[3][3], g3, p3);
        }
    }

    #pragma unroll
    for (int r = 0; r < 4; r++) {
        int row = rowBase + 4 * ty + r;
        ull* dst = (ull*)(d_part + ((size_t)row * NCH + chunk) * NBP);
        dst[tx]       = acc[r][0];
        dst[tx + 36]  = acc[r][1];
        dst[tx + 72]  = acc[r][2];
        dst[tx + 108] = acc[r][3];
    }
}

// ---------------- K3: one block per row; thread = bin (unchanged) ------------
#define LT 160   // threads (5 warps); bins 0..143 active
__global__ void __launch_bounds__(LT) k_loss(const int* __restrict__ hr) {
    __shared__ float sh[8];
    __shared__ float shH;
    int tid = threadIdx.x;
    int lane = tid & 31, warp = tid >> 5;
    int row = blockIdx.x;
    bool valid = tid < NB;

    float s = 0.f, c = 0.f;
    if (valid) {
        const float2* pr = d_part + (size_t)row * NCH * NBP + tid;
        #pragma unroll
        for (int ch = 0; ch < NCH; ch++) {
            float2 v = pr[ch * NBP];
            s += v.x; c += v.y;
        }
    }
    float ca = valid ? (s * s + c * c) : 0.f;

    float v = wallsum(ca);
    if (lane == 0) sh[warp] = v;
    __syncthreads();
    float tot = sh[0] + sh[1] + sh[2] + sh[3] + sh[4];
    __syncthreads();

    float logit = ca / tot;

    v = wallmax(valid ? logit : -1e30f);
    if (lane == 0) sh[warp] = v;
    __syncthreads();
    float mx = fmaxf(fmaxf(fmaxf(sh[0], sh[1]), fmaxf(sh[2], sh[3])), sh[4]);
    __syncthreads();

    v = wallsum(valid ? expf(logit - mx) : 0.f);
    if (lane == 0) sh[warp] = v;
    __syncthreads();
    float lse = mx + logf(sh[0] + sh[1] + sh[2] + sh[3] + sh[4]);

    int h = hr[row];
    if (tid == h) shH = logit;
    __syncthreads();
    float ce = lse - shH;
    __syncthreads();

    float klc = 0.f;
    if (valid) {
        float dd = (float)tid - (float)h;
        float t = expf(-0.5f * dd * dd) * 0.3989422804014327f;
        t = fmaxf(t, 1e-15f);
        klc = expf(t) * (t - (logit - lse));
    }
    v = wallsum(klc);
    if (lane == 0) sh[warp] = v;
    __syncthreads();
    if (tid == 0) d_fl[row] = ce + (sh[0] + sh[1] + sh[2] + sh[3] + sh[4]) / (float)NB;
}

// ---------------- K4: final scalar (unchanged) ----------------
__global__ void __launch_bounds__(1024) k_final(const int* __restrict__ epoch_p,
                                                float* __restrict__ out) {
    __shared__ float r1[32], r2[32];
    int tid = threadIdx.x, lane = tid & 31, warp = tid >> 5;
    float a = d_tl[tid], c = d_fl[tid];
    a = wsum(a); c = wsum(c);
    if (lane == 0) { r1[warp] = a; r2[warp] = c; }
    __syncthreads();
    if (warp == 0) {
        a = wsum(r1[lane]);
        c = wsum(r2[lane]);
        if (lane == 0) {
            float tl = a / (float)BB;
            float fl = c / (float)BB;
            int epoch = epoch_p[0];
            float alpha, beta;
            if (epoch > 25) { alpha = 0.05f; beta = 2.0f; }
            else {
                float e = (float)epoch * 0.04f;       // epoch/25
                alpha = 0.1f * exp2f(-e);
                beta  = exp2f(e);
            }
            out[0] = alpha * tl + beta * fl;
        }
    }
}

// ---------------- launch ----------------
extern "C" void kernel_launch(void* const* d_in, const int* in_sizes, int n_in,
                              void* d_out, int out_size) {
    const int*   epoch_p = nullptr;
    const float* xp = nullptr;
    const float* yp = nullptr;
    const int*   hrp = nullptr;
    for (int i = 0; i < n_in; i++) {
        if (in_sizes[i] == 1 && !epoch_p) epoch_p = (const int*)d_in[i];
        else if (in_sizes[i] == BB * NN) { if (!xp) xp = (const float*)d_in[i]; else yp = (const float*)d_in[i]; }
        else if (in_sizes[i] == BB) hrp = (const int*)d_in[i];
    }
    float* out = (float*)d_out;

    k_fold<<<BB, 256>>>(xp, yp);
    k_dft<<<dim3(32, NCH), 288>>>();
    k_loss<<<BB, LT>>>(hrp);
    k_final<<<1, 1024>>>(epoch_p, out);
    (void)out_size;
}

// round 14
// speedup vs baseline: 1.2848x; 1.0739x over previous
#include <cuda_runtime.h>
#include <math.h>
#include <stdint.h>

#define BB    1024     // batch rows
#define NN    8192     // samples per row
#define MM2   900      // parity-fold period
#define MM3   486      // reflection-folded m range (451 used, padded to 9*54)
#define NB    140      // bpm bins
#define NBP   144      // padded bins
#define NCH   9        // m-chunks
#define CHM   54       // m per chunk (9*54 = 486)
#define SLAB  9        // m per smem slab (6 steps)

// ---------------- device scratch ----------------
__device__ float4 d_fold[(size_t)BB * MM3];             // (ve,ue,vo,uo) per (row,m)
__device__ float2 d_part[(size_t)BB * NCH * NBP];       // [row][chunk][bin] (S,C)
__device__ float  d_tl[BB];
__device__ float  d_fl[BB];

typedef unsigned long long ull;

// ---------------- f32x2 helpers ----------------
__device__ __forceinline__ ull pk2(float lo, float hi) {
    ull r;
    asm("mov.b64 %0, {%1, %2};" : "=l"(r) : "f"(lo), "f"(hi));
    return r;
}
__device__ __forceinline__ void upk2(float& lo, float& hi, ull v) {
    asm("mov.b64 {%0, %1}, %2;" : "=f"(lo), "=f"(hi) : "l"(v));
}
__device__ __forceinline__ void fma2(ull& d, ull a, ull b) {
    asm("fma.rn.f32x2 %0, %1, %2, %0;" : "+l"(d) : "l"(a), "l"(b));
}
__device__ __forceinline__ ull add2(ull a, ull b) {
    ull r;
    asm("add.rn.f32x2 %0, %1, %2;" : "=l"(r) : "l"(a), "l"(b));
    return r;
}
__device__ __forceinline__ ull mul2(ull a, ull b) {
    ull r;
    asm("mul.rn.f32x2 %0, %1, %2;" : "=l"(r) : "l"(a), "l"(b));
    return r;
}
__device__ __forceinline__ float sum2(ull v) {
    float lo, hi; upk2(lo, hi, v); return lo + hi;
}

// ---------------- warp helpers ----------------
__device__ __forceinline__ float wsum(float v) {
    #pragma unroll
    for (int o = 16; o; o >>= 1) v += __shfl_down_sync(0xffffffffu, v, o);
    return v;
}
__device__ __forceinline__ float wallsum(float v) {
    #pragma unroll
    for (int o = 16; o; o >>= 1) v += __shfl_xor_sync(0xffffffffu, v, o);
    return v;
}
__device__ __forceinline__ float wallmax(float v) {
    #pragma unroll
    for (int o = 16; o; o >>= 1) v = fmaxf(v, __shfl_xor_sync(0xffffffffu, v, o));
    return v;
}

// ---------------- K1: pearson + parity fold (f32x2-packed) + reflection ------
// thread t<225 computes ge/go for m in {4t..4t+3}; stage in smem; emit combos
__global__ void __launch_bounds__(256) k_fold(const float* __restrict__ x,
                                              const float* __restrict__ y) {
    __shared__ float sge[MM2];
    __shared__ float sgo[MM2];
    __shared__ float red[8][5];
    int b = blockIdx.x;
    int tid = threadIdx.x;
    int lane = tid & 31, warp = tid >> 5;

    const float4* xr = (const float4*)(x + (size_t)b * NN);
    const float4* yr = (const float4*)(y + (size_t)b * NN);
    const float W = 3.8349520e-4f;          // pi/8191
    const ull NEG1 = pk2(-1.f, -1.f);

    ull ax0 = 0, ax1 = 0, ay0 = 0, ay1 = 0;        // sum x, sum y
    ull axx0 = 0, axx1 = 0, ayy0 = 0, ayy1 = 0;    // sum x^2, y^2
    ull axy0 = 0, axy1 = 0;                        // sum xy
    ull ge0 = 0, ge1 = 0, go0 = 0, go1 = 0;        // fold accumulators

    if (tid < 225) {
        #pragma unroll
        for (int j = 0; j < 10; j++) {
            int q = tid + 225 * j;
            if (j < 9 || q < 2048) {
                float4 xv = xr[q];
                float4 yv = yr[q];
                ull xp0 = pk2(xv.x, xv.y), xp1 = pk2(xv.z, xv.w);
                ull yp0 = pk2(yv.x, yv.y), yp1 = pk2(yv.z, yv.w);
                ax0 = add2(ax0, xp0);  ax1 = add2(ax1, xp1);
                ay0 = add2(ay0, yp0);  ay1 = add2(ay1, yp1);
                fma2(axx0, xp0, xp0);  fma2(axx1, xp1, xp1);
                fma2(ayy0, yp0, yp0);  fma2(ayy1, yp1, yp1);
                fma2(axy0, xp0, yp0);  fma2(axy1, xp1, yp1);

                int n = 4 * q;
                float s0 = __sinf((float)(n)     * W);
                float s1 = __sinf((float)(n + 1) * W);
                float s2 = __sinf((float)(n + 2) * W);
                float s3 = __sinf((float)(n + 3) * W);
                ull sp0 = pk2(s0, s1), sp1 = pk2(s2, s3);
                sp0 = mul2(sp0, sp0);  sp1 = mul2(sp1, sp1);   // sin^2
                ull h0 = mul2(xp0, sp0), h1 = mul2(xp1, sp1);  // hann-weighted x
                ge0 = add2(ge0, h0);  ge1 = add2(ge1, h1);
                if (j & 1) { fma2(go0, h0, NEG1); fma2(go1, h1, NEG1); }
                else       { go0 = add2(go0, h0); go1 = add2(go1, h1); }
            }
        }
        float g0, g1, g2, g3, o0, o1, o2, o3;
        upk2(g0, g1, ge0); upk2(g2, g3, ge1);
        upk2(o0, o1, go0); upk2(o2, o3, go1);
        sge[4 * tid]     = g0;  sgo[4 * tid]     = o0;
        sge[4 * tid + 1] = g1;  sgo[4 * tid + 1] = o1;
        sge[4 * tid + 2] = g2;  sgo[4 * tid + 2] = o2;
        sge[4 * tid + 3] = g3;  sgo[4 * tid + 3] = o3;
    }
    __syncthreads();

    // reflection combos: even f: (v,u)=(g[m]-g[900-m], g[m]+g[900-m])
    //                    odd  f: (v,u)=(g[m]+g[900-m], g[m]-g[900-m])
    for (int m = tid; m < MM3; m += 256) {
        float4 o;
        if (m == 0) {
            o = make_float4(sge[0], sge[0], sgo[0], sgo[0]);   // sin(0)=0: v unused
        } else if (m < 450) {
            float a = sge[m], bb2 = sge[900 - m];
            float c = sgo[m], d  = sgo[900 - m];
            o = make_float4(a - bb2, a + bb2, c + d, c - d);
        } else if (m == 450) {
            o = make_float4(sge[450], sge[450], sgo[450], sgo[450]);
        } else {
            o = make_float4(0.f, 0.f, 0.f, 0.f);
        }
        d_fold[(size_t)b * MM3 + m] = o;
    }

    float sx = sum2(ax0) + sum2(ax1);
    float sy = sum2(ay0) + sum2(ay1);
    float sxx = sum2(axx0) + sum2(axx1);
    float syy = sum2(ayy0) + sum2(ayy1);
    float sxy = sum2(axy0) + sum2(axy1);

    sx = wsum(sx); sy = wsum(sy); sxy = wsum(sxy); sxx = wsum(sxx); syy = wsum(syy);
    if (lane == 0) { red[warp][0]=sx; red[warp][1]=sy; red[warp][2]=sxy; red[warp][3]=sxx; red[warp][4]=syy; }
    __syncthreads();
    if (tid == 0) {
        double SX=0, SY=0, SXY=0, SXX=0, SYY=0;
        #pragma unroll
        for (int w = 0; w < 8; w++) {
            SX += red[w][0]; SY += red[w][1]; SXY += red[w][2];
            SXX += red[w][3]; SYY += red[w][4];
        }
        double num = (double)NN * SXY - SX * SY;
        double den = sqrt(((double)NN * SXX - SX * SX) * ((double)NN * SYY - SY * SY));
        d_tl[b] = (float)(1.0 - num / den);
    }
}

// ---------------- K2: reflected parity NUDFT (R13 verbatim) ------------------
// grid (32 tiles, 9 chunks), block 288 = 36 tx * 8 ty; tile 4 rows x 4 bins
__global__ void __launch_bounds__(288, 2) k_dft() {
    __shared__ float sTab[SLAB * 2 * NBP];    // 9 m x 144 bins x (s,c) interleaved
    __shared__ ull   sGE[SLAB][32];           // (ve,ue) packed
    __shared__ ull   sGO[SLAB][32];           // (vo,uo) packed

    int tile  = blockIdx.x;
    int chunk = blockIdx.y;
    int tid = threadIdx.x;
    int tx = tid % 36;
    int ty = tid / 36;

    int rowBase = tile * 32;
    int mBase = chunk * CHM;

    int bk  = tid % NBP;
    int grp = tid / NBP;
    int freq = 40 + bk;

    ull acc[4][4] = {};
    const ull* gbase = (tx & 1) ? &sGO[0][0] : &sGE[0][0];
    const float ASCALE = 3.4906585e-3f;   // 2*pi/1800

    for (int step = 0; step < CHM / SLAB; step++) {
        int m0 = mBase + step * SLAB;
        __syncthreads();
        #pragma unroll
        for (int i = 0; i < 5; i++) {
            int mi = grp * 5 + i;
            if (mi < SLAB) {
                float s = 0.f, c = 0.f;
                if (bk < NB) {
                    int r = (freq * (m0 + mi)) % 1800;
                    if (r >= 900) r -= 1800;
                    __sincosf((float)r * ASCALE, &s, &c);
                }
                sTab[mi * (2 * NBP) + 2 * bk]     = s;
                sTab[mi * (2 * NBP) + 2 * bk + 1] = c;
            }
        }
        {
            int r = tid & 31, mi = tid >> 5;
            float4 v = d_fold[(size_t)(rowBase + r) * MM3 + m0 + mi];
            sGE[mi][r] = pk2(v.x, v.y);
            sGO[mi][r] = pk2(v.z, v.w);
        }
        __syncthreads();

        #pragma unroll
        for (int mi = 0; mi < SLAB; mi++) {
            const ull* gq = gbase + mi * 32 + 4 * ty;
            ull g0 = gq[0], g1 = gq[1], g2 = gq[2], g3 = gq[3];
            const ull* trow = (const ull*)&sTab[mi * (2 * NBP)];
            ull p0 = trow[tx];
            ull p1 = trow[tx + 36];
            ull p2 = trow[tx + 72];
            ull p3 = trow[tx + 108];
            fma2(acc[0][0], g0, p0); fma2(acc[0][1], g0, p1);
            fma2(acc[0][2], g0, p2); fma2(acc[0][3], g0, p3);
            fma2(acc[1][0], g1, p0); fma2(acc[1][1], g1, p1);
            fma2(acc[1][2], g1, p2); fma2(acc[1][3], g1, p3);
            fma2(acc[2][0], g2, p0); fma2(acc[2][1], g2, p1);
            fma2(acc[2][2], g2, p2); fma2(acc[2][3], g2, p3);
            fma2(acc[3][0], g3, p0); fma2(acc[3][1], g3, p1);
            fma2(acc[3][2], g3, p2); fma2(acc[3][3], g3, p3);
        }
    }

    #pragma unroll
    for (int r = 0; r < 4; r++) {
        int row = rowBase + 4 * ty + r;
        ull* dst = (ull*)(d_part + ((size_t)row * NCH + chunk) * NBP);
        dst[tx]       = acc[r][0];
        dst[tx + 36]  = acc[r][1];
        dst[tx + 72]  = acc[r][2];
        dst[tx + 108] = acc[r][3];
    }
}

// ---------------- K3: one block per row; thread = bin (unchanged) ------------
#define LT 160   // threads (5 warps); bins 0..143 active
__global__ void __launch_bounds__(LT) k_loss(const int* __restrict__ hr) {
    __shared__ float sh[8];
    __shared__ float shH;
    int tid = threadIdx.x;
    int lane = tid & 31, warp = tid >> 5;
    int row = blockIdx.x;
    bool valid = tid < NB;

    float s = 0.f, c = 0.f;
    if (valid) {
        const float2* pr = d_part + (size_t)row * NCH * NBP + tid;
        #pragma unroll
        for (int ch = 0; ch < NCH; ch++) {
            float2 v = pr[ch * NBP];
            s += v.x; c += v.y;
        }
    }
    float ca = valid ? (s * s + c * c) : 0.f;

    float v = wallsum(ca);
    if (lane == 0) sh[warp] = v;
    __syncthreads();
    float tot = sh[0] + sh[1] + sh[2] + sh[3] + sh[4];
    __syncthreads();

    float logit = ca / tot;

    v = wallmax(valid ? logit : -1e30f);
    if (lane == 0) sh[warp] = v;
    __syncthreads();
    float mx = fmaxf(fmaxf(fmaxf(sh[0], sh[1]), fmaxf(sh[2], sh[3])), sh[4]);
    __syncthreads();

    v = wallsum(valid ? expf(logit - mx) : 0.f);
    if (lane == 0) sh[warp] = v;
    __syncthreads();
    float lse = mx + logf(sh[0] + sh[1] + sh[2] + sh[3] + sh[4]);

    int h = hr[row];
    if (tid == h) shH = logit;
    __syncthreads();
    float ce = lse - shH;
    __syncthreads();

    float klc = 0.f;
    if (valid) {
        float dd = (float)tid - (float)h;
        float t = expf(-0.5f * dd * dd) * 0.3989422804014327f;
        t = fmaxf(t, 1e-15f);
        klc = expf(t) * (t - (logit - lse));
    }
    v = wallsum(klc);
    if (lane == 0) sh[warp] = v;
    __syncthreads();
    if (tid == 0) d_fl[row] = ce + (sh[0] + sh[1] + sh[2] + sh[3] + sh[4]) / (float)NB;
}

// ---------------- K4: final scalar (unchanged) ----------------
__global__ void __launch_bounds__(1024) k_final(const int* __restrict__ epoch_p,
                                                float* __restrict__ out) {
    __shared__ float r1[32], r2[32];
    int tid = threadIdx.x, lane = tid & 31, warp = tid >> 5;
    float a = d_tl[tid], c = d_fl[tid];
    a = wsum(a); c = wsum(c);
    if (lane == 0) { r1[warp] = a; r2[warp] = c; }
    __syncthreads();
    if (warp == 0) {
        a = wsum(r1[lane]);
        c = wsum(r2[lane]);
        if (lane == 0) {
            float tl = a / (float)BB;
            float fl = c / (float)BB;
            int epoch = epoch_p[0];
            float alpha, beta;
            if (epoch > 25) { alpha = 0.05f; beta = 2.0f; }
            else {
                float e = (float)epoch * 0.04f;       // epoch/25
                alpha = 0.1f * exp2f(-e);
                beta  = exp2f(e);
            }
            out[0] = alpha * tl + beta * fl;
        }
    }
}

// ---------------- launch ----------------
extern "C" void kernel_launch(void* const* d_in, const int* in_sizes, int n_in,
                              void* d_out, int out_size) {
    const int*   epoch_p = nullptr;
    const float* xp = nullptr;
    const float* yp = nullptr;
    const int*   hrp = nullptr;
    for (int i = 0; i < n_in; i++) {
        if (in_sizes[i] == 1 && !epoch_p) epoch_p = (const int*)d_in[i];
        else if (in_sizes[i] == BB * NN) { if (!xp) xp = (const float*)d_in[i]; else yp = (const float*)d_in[i]; }
        else if (in_sizes[i] == BB) hrp = (const int*)d_in[i];
    }
    float* out = (float*)d_out;

    k_fold<<<BB, 256>>>(xp, yp);
    k_dft<<<dim3(32, NCH), 288>>>();
    k_loss<<<BB, LT>>>(hrp);
    k_final<<<1, 1024>>>(epoch_p, out);
    (void)out_size;
}